// round 3
// baseline (speedup 1.0000x reference)
#include <cuda_runtime.h>

#define FULL 0xFFFFFFFFu

namespace {
constexpr int BATCH = 256;
constexpr int MAXT  = 512;
constexpr int T1    = MAXT + 1;      // 513
constexpr int S     = 64;
constexpr int NPOS  = BATCH * T1;    // 131328
constexpr int TPOS  = 16;            // positions per CTA in phase 1
constexpr int NCTA1 = NPOS / TPOS;   // 8208 (exact)
}

// Per position: 16 x float4 {asel, beta, omb, start} — 33.6 MB scratch.
__device__ float4 g_mid[NPOS * 16];
__device__ float  g_batch[BATCH];

// ---------------------------------------------------------------------------
// Phase 1: fused GEMV (304 cols) + log-softmax + action gather, 16 pos / CTA.
// 160 threads: 128 action (2 cols each: c, c+128), 16 stop (STOP/CONT pair
// in-thread -> local softmax, no shfl), 16 start (1 col each).
// Compile-time W strides; 2 cols/thread halves LDS broadcast traffic.
// ---------------------------------------------------------------------------
__global__ __launch_bounds__(160, 4) void phase1_kernel(
    const float* __restrict__ s_i,
    const int*   __restrict__ actions,
    const int*   __restrict__ lengths,
    const float* __restrict__ Wa, const float* __restrict__ ba,
    const float* __restrict__ Ws, const float* __restrict__ bs,
    const float* __restrict__ Wst, const float* __restrict__ bst)
{
    __shared__ __align__(16) float sh_s[TPOS][S];
    __shared__ __align__(16) float sh_out[TPOS][64];
    __shared__ int sh_act[TPOS];
    __shared__ int sh_skip;

    const int tid  = threadIdx.x;
    const int pos0 = blockIdx.x * TPOS;

    // Dead-tile check (phase 2 never reads t > lengths[b]) + action gather.
    if (tid < 32) {
        int pos = pos0 + (tid & 15);
        int b = pos / T1;
        int t = pos - b * T1;
        bool need = (tid < 16) && (t <= __ldg(&lengths[b]));
        unsigned m = __ballot_sync(FULL, need);
        if (tid == 0) sh_skip = (m == 0) ? 1 : 0;
        if (tid < 16) sh_act[tid] = (t < MAXT) ? __ldg(&actions[b * MAXT + t]) : 0;
    }
    // Stage the s tile: 16 pos x 64 floats = 256 float4, coalesced.
    #pragma unroll
    for (int i = tid; i < TPOS * (S / 4); i += 160) {
        ((float4*)sh_s)[i] = ((const float4*)s_i)[pos0 * (S / 4) + i];
    }
    __syncthreads();
    if (sh_skip) return;

    const int warp = tid >> 5;
    const int lane = tid & 31;

    if (warp < 4) {
        // ---- action: 2 columns per thread (c0 = tid, c1 = tid + 128) ----
        const float* w = Wa + tid;
        float acc0[TPOS], acc1[TPOS];
        {
            float b0 = __ldg(&ba[tid]), b1 = __ldg(&ba[tid + 128]);
            #pragma unroll
            for (int p = 0; p < TPOS; p++) { acc0[p] = b0; acc1[p] = b1; }
        }
        #pragma unroll 2
        for (int s4 = 0; s4 < S; s4 += 4) {
            float u0 = __ldg(&w[(s4 + 0) * 256]);
            float u1 = __ldg(&w[(s4 + 1) * 256]);
            float u2 = __ldg(&w[(s4 + 2) * 256]);
            float u3 = __ldg(&w[(s4 + 3) * 256]);
            float v0 = __ldg(&w[(s4 + 0) * 256 + 128]);
            float v1 = __ldg(&w[(s4 + 1) * 256 + 128]);
            float v2 = __ldg(&w[(s4 + 2) * 256 + 128]);
            float v3 = __ldg(&w[(s4 + 3) * 256 + 128]);
            #pragma unroll
            for (int p = 0; p < TPOS; p++) {
                float4 sv = *(const float4*)&sh_s[p][s4];   // LDS.128 broadcast
                acc0[p] = fmaf(sv.w, u3, fmaf(sv.z, u2, fmaf(sv.y, u1, fmaf(sv.x, u0, acc0[p]))));
                acc1[p] = fmaf(sv.w, v3, fmaf(sv.z, v2, fmaf(sv.y, v1, fmaf(sv.x, v0, acc1[p]))));
            }
        }
        // Log-softmax over 16 lanes (no max pass: |z| ~ 6 max, fp32-safe),
        // two independent reductions interleaved for ILP.
        const int a   = tid & 15;
        const int nb0 = (tid >> 4) & 7;
        const int nb1 = nb0 + 8;
        #pragma unroll 2
        for (int p = 0; p < TPOS; p++) {
            float e0 = __expf(acc0[p]);
            float e1 = __expf(acc1[p]);
            #pragma unroll
            for (int d = 8; d; d >>= 1) {
                e0 += __shfl_xor_sync(FULL, e0, d);
                e1 += __shfl_xor_sync(FULL, e1, d);
            }
            float l0 = __logf(e0), l1 = __logf(e1);
            if (a == sh_act[p]) {
                sh_out[p][nb0 * 4 + 0] = acc0[p] - l0;      // asel (nb0)
                sh_out[p][nb1 * 4 + 0] = acc1[p] - l1;      // asel (nb1)
            }
        }
    } else if (lane < 16) {
        // ---- stop: cols (2t, 2t+1) = (STOP, CONT) of nb = t, in-thread ----
        const int t = lane;
        const float2* w = (const float2*)Ws + t;            // elem (s,2t) pair
        float acc0[TPOS], acc1[TPOS];
        {
            float2 bv = __ldg(&((const float2*)bs)[t]);
            #pragma unroll
            for (int p = 0; p < TPOS; p++) { acc0[p] = bv.x; acc1[p] = bv.y; }
        }
        #pragma unroll 2
        for (int s4 = 0; s4 < S; s4 += 4) {
            float2 w0 = __ldg(&w[(s4 + 0) * 16]);
            float2 w1 = __ldg(&w[(s4 + 1) * 16]);
            float2 w2 = __ldg(&w[(s4 + 2) * 16]);
            float2 w3 = __ldg(&w[(s4 + 3) * 16]);
            #pragma unroll
            for (int p = 0; p < TPOS; p++) {
                float4 sv = *(const float4*)&sh_s[p][s4];
                acc0[p] = fmaf(sv.w, w3.x, fmaf(sv.z, w2.x, fmaf(sv.y, w1.x, fmaf(sv.x, w0.x, acc0[p]))));
                acc1[p] = fmaf(sv.w, w3.y, fmaf(sv.z, w2.y, fmaf(sv.y, w1.y, fmaf(sv.x, w0.y, acc1[p]))));
            }
        }
        #pragma unroll 2
        for (int p = 0; p < TPOS; p++) {
            float z0 = acc0[p], z1 = acc1[p];
            float l = __logf(__expf(z0) + __expf(z1));      // local pair LSE
            sh_out[p][t * 4 + 1] = z0 - l;                  // beta (STOP)
            sh_out[p][t * 4 + 2] = z1 - l;                  // omb (CONTINUE)
        }
    } else {
        // ---- start: one col per thread, c = lane - 16, lanes 16..31 ----
        const int c = lane - 16;
        const float* w = Wst + c;
        float acc[TPOS];
        {
            float bv = __ldg(&bst[c]);
            #pragma unroll
            for (int p = 0; p < TPOS; p++) acc[p] = bv;
        }
        #pragma unroll 2
        for (int s4 = 0; s4 < S; s4 += 4) {
            float w0 = __ldg(&w[(s4 + 0) * 16]);
            float w1 = __ldg(&w[(s4 + 1) * 16]);
            float w2 = __ldg(&w[(s4 + 2) * 16]);
            float w3 = __ldg(&w[(s4 + 3) * 16]);
            #pragma unroll
            for (int p = 0; p < TPOS; p++) {
                float4 sv = *(const float4*)&sh_s[p][s4];
                acc[p] = fmaf(sv.w, w3, fmaf(sv.z, w2, fmaf(sv.y, w1, fmaf(sv.x, w0, acc[p]))));
            }
        }
        #pragma unroll 2
        for (int p = 0; p < TPOS; p++) {
            float e = __expf(acc[p]);
            #pragma unroll
            for (int d = 8; d; d >>= 1) e += __shfl_xor_sync(0xFFFF0000u, e, d);
            sh_out[p][c * 4 + 3] = acc[p] - __logf(e);      // start
        }
    }
    __syncthreads();

    // Vectorized, coalesced flush of the staged tile.
    #pragma unroll
    for (int i = tid; i < TPOS * 16; i += 160) {
        g_mid[pos0 * 16 + i] = ((const float4*)sh_out)[i];
    }
}

// ---------------------------------------------------------------------------
// Phase 2: serial HMM recursion, one warp per batch element.
// Lanes 0..15 hold the 16 states (16..31 mirror so FULL-mask shfl works).
// Recentred each step by the step's own LSE; critical path shortened by
// computing exp(f+omb) and exp(start) OFF the reduction chain:
//   f' = log(exp(f+ot) + exp(st)*e) - lse + at,   e = sum_k exp(f_k+bt_k).
// ---------------------------------------------------------------------------
__global__ __launch_bounds__(32) void phase2_kernel(const int* __restrict__ lengths)
{
    const int b    = blockIdx.x;
    const int lane = threadIdx.x;
    const int j    = lane & 15;

    const float4* mid = g_mid + (size_t)b * T1 * 16 + j;
    const int L = __ldg(&lengths[b]);         // 1..512

    float4 v0 = *mid;
    float f = v0.w + v0.x;                    // start[0] + asel[0]
    float C = 0.0f;                           // accumulated recentring offset
    const float4* p = mid + 16;
    float4 nxt = *p;                          // prefetch t=1 (always valid)

    for (int t = 1; t < L; t++) {
        float4 v = nxt;
        p += 16;
        nxt = *p;                             // t+1 <= L <= 512 < T1, valid

        float t2 = __expf(f + v.z);           // exp(f + omb)   — off chain
        float se = __expf(v.w);               // exp(start)     — off chain
        float e  = __expf(f + v.y);           // exp(f + beta)
        #pragma unroll
        for (int d = 8; d; d >>= 1) e += __shfl_xor_sync(FULL, e, d);
        float lse = __logf(e);                // parallel with fma+log below
        f = __logf(fmaf(se, e, t2)) - lse + v.x;
        C += lse;
    }

    // After the loop, nxt holds position t = L (holds for L == 1 too).
    float4 vL = nxt;
    float e = __expf(f + vL.y);               // x0 + x1 (beta at t = L)
    #pragma unroll
    for (int d = 8; d; d >>= 1) e += __shfl_xor_sync(FULL, e, d);
    if (lane == 0) g_batch[b] = C + __logf(e);
}

// ---------------------------------------------------------------------------
// Phase 3: deterministic fixed-order reduction of 256 per-batch terms.
// ---------------------------------------------------------------------------
__global__ __launch_bounds__(256) void finalize_kernel(float* __restrict__ out)
{
    __shared__ float sh[BATCH];
    int t = threadIdx.x;
    sh[t] = g_batch[t];
    __syncthreads();
    #pragma unroll
    for (int s = 128; s > 0; s >>= 1) {
        if (t < s) sh[t] += sh[t + s];
        __syncthreads();
    }
    if (t == 0) out[0] = -sh[0];
}

// ---------------------------------------------------------------------------
// d_in order: s_i_batch, actions_batch, lengths, W_action, b_action,
//             W_stop, b_stop, W_start, b_start
// ---------------------------------------------------------------------------
extern "C" void kernel_launch(void* const* d_in, const int* in_sizes, int n_in,
                              void* d_out, int out_size)
{
    const float* s_i     = (const float*)d_in[0];
    const int*   actions = (const int*)d_in[1];
    const int*   lengths = (const int*)d_in[2];
    const float* Wa      = (const float*)d_in[3];
    const float* ba      = (const float*)d_in[4];
    const float* Ws      = (const float*)d_in[5];
    const float* bs      = (const float*)d_in[6];
    const float* Wst     = (const float*)d_in[7];
    const float* bst     = (const float*)d_in[8];

    phase1_kernel<<<NCTA1, 160>>>(s_i, actions, lengths, Wa, ba, Ws, bs, Wst, bst);
    phase2_kernel<<<BATCH, 32>>>(lengths);
    finalize_kernel<<<1, BATCH>>>((float*)d_out);
}

// round 5
// speedup vs baseline: 2.5579x; 2.5579x over previous
#include <cuda_runtime.h>
#include <cuda_bf16.h>
#include <cstdint>

#define FULL 0xFFFFFFFFu

namespace {
constexpr int BATCH = 256;
constexpr int MAXT  = 512;
constexpr int T1    = MAXT + 1;      // 513
constexpr int S     = 64;
constexpr int NPOS  = BATCH * T1;    // 131328
constexpr int TILE_M = 128;          // positions per phase-1 CTA
constexpr int NCTA1 = NPOS / TILE_M; // 1026 exact
constexpr int NBC   = 304;           // real logit columns
constexpr int PITCH = 72;            // bf16 row pitch (64 + 8 pad): conflict-free ldmatrix

// dynamic smem layout (bytes)
constexpr int SM_A     = 0;                       // union: A bf16 [128][72] (18432) / staging f32 [128][64] (32768)
constexpr int SM_B     = 32768;                   // W^T bf16 [304][72] = 43776
constexpr int SM_BIAS  = SM_B + 43776;            // 76544: 304 f32 (pad to 1280)
constexpr int SM_ACT   = SM_BIAS + 1280;          // 77824: 128 int
constexpr int SM_TOTAL = SM_ACT + 512;            // 78336
}

// Per position: 16 x float4 {asel, beta, omb, start} — 33.6 MB scratch.
__device__ float4 g_mid[NPOS * 16];
__device__ float  g_batch[BATCH];
// Pre-transposed bf16 weight image W^T: [304 cols][72 pitch] (cols 64..71 unused).
__device__ __align__(16) __nv_bfloat16 g_B[NBC * PITCH];
__device__ float g_bias[NBC];

// ---------------------------------------------------------------------------
// Baseline-PTX helpers (sm_80-level: compile fine for compute_100)
// ---------------------------------------------------------------------------
__device__ __forceinline__ uint32_t cvta_smem(const void* p) {
    uint32_t a;
    asm("{ .reg .u64 t; cvta.to.shared.u64 t, %1; cvt.u32.u64 %0, t; }" : "=r"(a) : "l"(p));
    return a;
}
__device__ __forceinline__ void ldsm4(uint32_t* r, uint32_t addr) {
    asm volatile("ldmatrix.sync.aligned.m8n8.x4.shared.b16 {%0,%1,%2,%3}, [%4];"
                 : "=r"(r[0]), "=r"(r[1]), "=r"(r[2]), "=r"(r[3]) : "r"(addr));
}
__device__ __forceinline__ void mma16816(float* d, const uint32_t* a, const uint32_t* b) {
    asm volatile("mma.sync.aligned.m16n8k16.row.col.f32.bf16.bf16.f32 "
                 "{%0,%1,%2,%3}, {%4,%5,%6,%7}, {%8,%9}, {%0,%1,%2,%3};"
                 : "+f"(d[0]), "+f"(d[1]), "+f"(d[2]), "+f"(d[3])
                 : "r"(a[0]), "r"(a[1]), "r"(a[2]), "r"(a[3]), "r"(b[0]), "r"(b[1]));
}

// ---------------------------------------------------------------------------
// Prep: W^T bf16 image [304][72] + bias vector. 76 x 256 threads = 19456.
// ---------------------------------------------------------------------------
__global__ void prep_kernel(
    const float* __restrict__ Wa, const float* __restrict__ ba,
    const float* __restrict__ Ws, const float* __restrict__ bs,
    const float* __restrict__ Wst, const float* __restrict__ bst)
{
    int idx = blockIdx.x * blockDim.x + threadIdx.x;    // 0..19455
    if (idx < NBC) {
        float bv;
        if (idx < 256)      bv = __ldg(&ba[idx]);
        else if (idx < 288) bv = __ldg(&bs[idx - 256]);
        else                bv = __ldg(&bst[idx - 288]);
        g_bias[idx] = bv;
    }
    if (idx >= NBC * S) return;
    int n = idx >> 6, k = idx & 63;
    float w;
    if (n < 256)      w = __ldg(&Wa[k * 256 + n]);
    else if (n < 288) w = __ldg(&Ws[k * 32 + (n - 256)]);
    else              w = __ldg(&Wst[k * 16 + (n - 288)]);
    g_B[n * PITCH + k] = __float2bfloat16(w);
}

// ---------------------------------------------------------------------------
// Phase 1: bf16 HMMA GEMM (128 pos x 304 cols, K=64) + fused log-softmax.
// 8 warps; warp w owns rows m0 = 16w. 19 N-chunks of 16 cols:
//   chunks 0..15 action blocks, 16..17 stop pairs, 18 start.
// ---------------------------------------------------------------------------
__global__ __launch_bounds__(256, 2) void phase1_kernel(
    const float* __restrict__ s_i,
    const int*   __restrict__ actions,
    const int*   __restrict__ lengths)
{
    extern __shared__ __align__(16) unsigned char smem[];
    const int tid  = threadIdx.x;
    const int pos0 = blockIdx.x * TILE_M;

    int need = 0;
    if (tid < TILE_M) {
        int pos = pos0 + tid;
        int b = pos / T1;
        int t = pos - b * T1;
        need = (t <= __ldg(&lengths[b]));
        ((int*)(smem + SM_ACT))[tid] = (t < MAXT) ? __ldg(&actions[b * MAXT + t]) : 0;
    }
    if (!__syncthreads_or(need)) return;

    // --- stage B (2736 uint4) ---
    {
        const uint4* src = (const uint4*)g_B;
        uint4* dst = (uint4*)(smem + SM_B);
        #pragma unroll
        for (int i = tid; i < NBC * PITCH * 2 / 16; i += 256) dst[i] = __ldg(&src[i]);
    }
    // --- stage bias ---
    {
        float* dst = (float*)(smem + SM_BIAS);
        for (int i = tid; i < NBC; i += 256) dst[i] = g_bias[i];
    }
    // --- stage A: fp32 -> bf16, [128][72] pitch ---
    {
        const float2* src = (const float2*)(s_i + (size_t)pos0 * S);
        __nv_bfloat16* A = (__nv_bfloat16*)(smem + SM_A);
        #pragma unroll
        for (int i = tid; i < TILE_M * (S / 2); i += 256) {
            int row = i >> 5, cp = i & 31;
            float2 v = __ldg(&src[i]);
            __nv_bfloat162 h = __floats2bfloat162_rn(v.x, v.y);
            *(uint32_t*)(A + row * PITCH + 2 * cp) = *(uint32_t*)&h;
        }
    }
    __syncthreads();

    const int wid = tid >> 5, lane = tid & 31;
    const int g = lane >> 2, tig = lane & 3;
    const int m0 = wid * 16;
    const uint32_t sb = cvta_smem(smem);

    // --- A fragments: 4 k-steps, each m16k16 via ldmatrix.x4 ---
    uint32_t afrag[4][4];
    {
        int r  = m0 + (lane & 7) + ((lane >> 3) & 1) * 8;
        int kc = ((lane >> 4) & 1) * 8;
        uint32_t base = sb + SM_A + (uint32_t)(r * PITCH + kc) * 2;
        #pragma unroll
        for (int s = 0; s < 4; s++) ldsm4(afrag[s], base + s * 32);
    }
    const int act_lo = ((const int*)(smem + SM_ACT))[m0 + g];
    const int act_hi = ((const int*)(smem + SM_ACT))[m0 + g + 8];
    __syncthreads();   // A smem region now becomes the f32 staging buffer

    float* sh_out = (float*)(smem + SM_A);              // [128][64]
    const float* biasS = (const float*)(smem + SM_BIAS);
    const int row_lo = m0 + g, row_hi = m0 + g + 8;

    #pragma unroll 1
    for (int c = 0; c < 19; c++) {
        const int n0 = c * 16;

        // B fragments for this 16-col chunk: 2 n-frags x 4 k-steps
        uint32_t bfrag[2][4][2];
        #pragma unroll
        for (int f = 0; f < 2; f++) {
            int n = n0 + f * 8 + (lane & 7);
            uint32_t base = sb + SM_B + (uint32_t)n * (PITCH * 2) + ((lane >> 3) & 3) * 16;
            uint32_t r[4];
            ldsm4(r, base);            // k 0..31
            bfrag[f][0][0] = r[0]; bfrag[f][0][1] = r[1];
            bfrag[f][1][0] = r[2]; bfrag[f][1][1] = r[3];
            ldsm4(r, base + 64);       // k 32..63
            bfrag[f][2][0] = r[0]; bfrag[f][2][1] = r[1];
            bfrag[f][3][0] = r[2]; bfrag[f][3][1] = r[3];
        }

        float acc0[4] = {0.f, 0.f, 0.f, 0.f};
        float acc1[4] = {0.f, 0.f, 0.f, 0.f};
        #pragma unroll
        for (int s = 0; s < 4; s++) {
            mma16816(acc0, afrag[s], bfrag[0][s]);
            mma16816(acc1, afrag[s], bfrag[1][s]);
        }

        // Bias (same 4 cols for both rows)
        float2 bv0 = *(const float2*)&biasS[n0 + 2 * tig];
        float2 bv1 = *(const float2*)&biasS[n0 + 8 + 2 * tig];
        // row_lo cols {2tig, 2tig+1, 8+2tig, 9+2tig}; row_hi same cols
        float zl0 = acc0[0] + bv0.x, zl1 = acc0[1] + bv0.y;
        float zl2 = acc1[0] + bv1.x, zl3 = acc1[1] + bv1.y;
        float zh0 = acc0[2] + bv0.x, zh1 = acc0[3] + bv0.y;
        float zh2 = acc1[2] + bv1.x, zh3 = acc1[3] + bv1.y;

        if (c < 16) {
            // ---- action block c: 16-wide softmax per row + gather ----
            int c0 = 2 * tig, c1 = c0 + 1, c2 = c0 + 8, c3 = c1 + 8;
            float el = __expf(zl0) + __expf(zl1) + __expf(zl2) + __expf(zl3);
            float eh = __expf(zh0) + __expf(zh1) + __expf(zh2) + __expf(zh3);
            float sl = (c0 == act_lo ? zl0 : 0.f) + (c1 == act_lo ? zl1 : 0.f)
                     + (c2 == act_lo ? zl2 : 0.f) + (c3 == act_lo ? zl3 : 0.f);
            float sh = (c0 == act_hi ? zh0 : 0.f) + (c1 == act_hi ? zh1 : 0.f)
                     + (c2 == act_hi ? zh2 : 0.f) + (c3 == act_hi ? zh3 : 0.f);
            el += __shfl_xor_sync(FULL, el, 1); el += __shfl_xor_sync(FULL, el, 2);
            eh += __shfl_xor_sync(FULL, eh, 1); eh += __shfl_xor_sync(FULL, eh, 2);
            sl += __shfl_xor_sync(FULL, sl, 1); sl += __shfl_xor_sync(FULL, sl, 2);
            sh += __shfl_xor_sync(FULL, sh, 1); sh += __shfl_xor_sync(FULL, sh, 2);
            if (tig == 0) {
                sh_out[row_lo * 64 + c * 4] = sl - __logf(el);
                sh_out[row_hi * 64 + c * 4] = sh - __logf(eh);
            }
        } else if (c < 18) {
            // ---- stop pairs: (z0,z1) = (STOP, CONT) both in-thread ----
            int jb0 = (n0 - 256) / 2 + tig;     // f = 0
            int jb1 = jb0 + 4;                  // f = 1
            float l;
            l = __logf(__expf(zl0) + __expf(zl1));
            sh_out[row_lo * 64 + jb0 * 4 + 1] = zl0 - l;
            sh_out[row_lo * 64 + jb0 * 4 + 2] = zl1 - l;
            l = __logf(__expf(zl2) + __expf(zl3));
            sh_out[row_lo * 64 + jb1 * 4 + 1] = zl2 - l;
            sh_out[row_lo * 64 + jb1 * 4 + 2] = zl3 - l;
            l = __logf(__expf(zh0) + __expf(zh1));
            sh_out[row_hi * 64 + jb0 * 4 + 1] = zh0 - l;
            sh_out[row_hi * 64 + jb0 * 4 + 2] = zh1 - l;
            l = __logf(__expf(zh2) + __expf(zh3));
            sh_out[row_hi * 64 + jb1 * 4 + 1] = zh2 - l;
            sh_out[row_hi * 64 + jb1 * 4 + 2] = zh3 - l;
        } else {
            // ---- start: 16-wide softmax per row, write all 16 ----
            float el = __expf(zl0) + __expf(zl1) + __expf(zl2) + __expf(zl3);
            float eh = __expf(zh0) + __expf(zh1) + __expf(zh2) + __expf(zh3);
            el += __shfl_xor_sync(FULL, el, 1); el += __shfl_xor_sync(FULL, el, 2);
            eh += __shfl_xor_sync(FULL, eh, 1); eh += __shfl_xor_sync(FULL, eh, 2);
            float ll = __logf(el), lh = __logf(eh);
            int c0 = 2 * tig, c2 = c0 + 8;
            sh_out[row_lo * 64 + c0 * 4 + 3]       = zl0 - ll;
            sh_out[row_lo * 64 + (c0 + 1) * 4 + 3] = zl1 - ll;
            sh_out[row_lo * 64 + c2 * 4 + 3]       = zl2 - ll;
            sh_out[row_lo * 64 + (c2 + 1) * 4 + 3] = zl3 - ll;
            sh_out[row_hi * 64 + c0 * 4 + 3]       = zh0 - lh;
            sh_out[row_hi * 64 + (c0 + 1) * 4 + 3] = zh1 - lh;
            sh_out[row_hi * 64 + c2 * 4 + 3]       = zh2 - lh;
            sh_out[row_hi * 64 + (c2 + 1) * 4 + 3] = zh3 - lh;
        }
    }

    // Per-warp flush of its own 16 rows (no CTA sync needed).
    {
        float4* dst = g_mid + (size_t)(pos0 + m0) * 16;
        const float4* src = (const float4*)(sh_out + m0 * 64);
        #pragma unroll
        for (int i = lane; i < 256; i += 32) dst[i] = src[i];
    }
}

// ---------------------------------------------------------------------------
// Phase 2: serial HMM recursion, one warp per batch element. Recentred each
// step by the step's own LSE; exp(f+omb)/exp(start) computed off-chain:
//   f' = log(exp(f+ot) + exp(st)*e) - lse + at,  e = sum_k exp(f_k + bt_k)
// ---------------------------------------------------------------------------
__global__ __launch_bounds__(32) void phase2_kernel(const int* __restrict__ lengths)
{
    const int b    = blockIdx.x;
    const int lane = threadIdx.x;
    const int j    = lane & 15;

    const float4* mid = g_mid + (size_t)b * T1 * 16 + j;
    const int L = __ldg(&lengths[b]);         // 1..512

    float4 v0 = *mid;
    float f = v0.w + v0.x;                    // start[0] + asel[0]
    float C = 0.0f;
    const float4* p = mid + 16;
    float4 nxt = *p;                          // prefetch t=1 (always valid)

    for (int t = 1; t < L; t++) {
        float4 v = nxt;
        p += 16;
        nxt = *p;

        float t2 = __expf(f + v.z);           // off critical chain
        float se = __expf(v.w);               // off critical chain
        float e  = __expf(f + v.y);
        #pragma unroll
        for (int d = 8; d; d >>= 1) e += __shfl_xor_sync(FULL, e, d);
        float lse = __logf(e);
        f = __logf(fmaf(se, e, t2)) - lse + v.x;
        C += lse;
    }

    float4 vL = nxt;                          // position t = L
    float e = __expf(f + vL.y);
    #pragma unroll
    for (int d = 8; d; d >>= 1) e += __shfl_xor_sync(FULL, e, d);
    if (lane == 0) g_batch[b] = C + __logf(e);
}

// ---------------------------------------------------------------------------
// Phase 3: deterministic fixed-order reduction of 256 per-batch terms.
// ---------------------------------------------------------------------------
__global__ __launch_bounds__(256) void finalize_kernel(float* __restrict__ out)
{
    __shared__ float sh[BATCH];
    int t = threadIdx.x;
    sh[t] = g_batch[t];
    __syncthreads();
    #pragma unroll
    for (int s = 128; s > 0; s >>= 1) {
        if (t < s) sh[t] += sh[t + s];
        __syncthreads();
    }
    if (t == 0) out[0] = -sh[0];
}

// ---------------------------------------------------------------------------
// d_in order: s_i_batch, actions_batch, lengths, W_action, b_action,
//             W_stop, b_stop, W_start, b_start
// ---------------------------------------------------------------------------
extern "C" void kernel_launch(void* const* d_in, const int* in_sizes, int n_in,
                              void* d_out, int out_size)
{
    (void)in_sizes; (void)n_in; (void)out_size;
    const float* s_i     = (const float*)d_in[0];
    const int*   actions = (const int*)d_in[1];
    const int*   lengths = (const int*)d_in[2];
    const float* Wa      = (const float*)d_in[3];
    const float* ba      = (const float*)d_in[4];
    const float* Ws      = (const float*)d_in[5];
    const float* bs      = (const float*)d_in[6];
    const float* Wst     = (const float*)d_in[7];
    const float* bst     = (const float*)d_in[8];

    static bool attr_set = false;
    if (!attr_set) {
        cudaFuncSetAttribute(phase1_kernel,
                             cudaFuncAttributeMaxDynamicSharedMemorySize, SM_TOTAL);
        attr_set = true;
    }

    prep_kernel<<<76, 256>>>(Wa, ba, Ws, bs, Wst, bst);
    phase1_kernel<<<NCTA1, 256, SM_TOTAL>>>(s_i, actions, lengths);
    phase2_kernel<<<BATCH, 32>>>(lengths);
    finalize_kernel<<<1, BATCH>>>((float*)d_out);
}